// round 13
// baseline (speedup 1.0000x reference)
#include <cuda_runtime.h>
#include <cuda_fp16.h>
#include <cstdint>

// Inputs:
//  d_in[0] pts            float32  [N_PTS, 3]
//  d_in[1] p2v_idx        int32    [N_PTS]
//  d_in[2] embeddings     float32  [N_EMB, 16]
//  d_in[3] center_points  float32  [N_VOX, 3]
//  d_in[4] center2corner  int32    [N_VOX, 8]
//  d_in[5] voxel_size     float32  [1]
// Output: float32 [N_PTS, 16]
//
// Exact R6 main (best main: 92.7us) + PDL overlap: main launches before prep
// finishes, does all prep-independent loads (p2v, pts, c2c), then
// griddepcontrol.wait before touching the fp16 emb / cp4 tables.
// fp16 emb table (rel_err ~2e-4 < 1e-3), evict_last on gathered tables.

#define N_EMB_MAX 1000000
#define N_VOX_MAX 500000
__device__ __align__(16) __half g_emb_h[N_EMB_MAX * 16];  // 32 MB
__device__ __align__(16) float4 g_cp4[N_VOX_MAX];         // 8 MB

// ---- cache-hint helpers ----
__device__ __forceinline__ uint64_t make_evict_last_policy() {
    uint64_t pol;
    asm("createpolicy.fractional.L2::evict_last.b64 %0, 1.0;" : "=l"(pol));
    return pol;
}
__device__ __forceinline__ uint2 ldg_last_u2(const void* p, uint64_t pol) {
    uint2 v;
    asm volatile("ld.global.nc.L2::cache_hint.v2.b32 {%0,%1}, [%2], %3;"
                 : "=r"(v.x), "=r"(v.y) : "l"(p), "l"(pol));
    return v;
}
__device__ __forceinline__ float4 ldg_last_f4(const float4* p, uint64_t pol) {
    float4 v;
    asm volatile("ld.global.nc.L2::cache_hint.v4.f32 {%0,%1,%2,%3}, [%4], %5;"
                 : "=f"(v.x), "=f"(v.y), "=f"(v.z), "=f"(v.w)
                 : "l"(p), "l"(pol));
    return v;
}
__device__ __forceinline__ void ldg_last_i8(const int* p, int* o) {
    asm volatile("ld.global.nc.L2::evict_last.v8.b32 "
                 "{%0,%1,%2,%3,%4,%5,%6,%7}, [%8];"
                 : "=r"(o[0]), "=r"(o[1]), "=r"(o[2]), "=r"(o[3]),
                   "=r"(o[4]), "=r"(o[5]), "=r"(o[6]), "=r"(o[7])
                 : "l"(p));
}
__device__ __forceinline__ float4 ldg_stream_f4(const float4* p) {
    float4 v;
    asm volatile("ld.global.cs.v4.f32 {%0,%1,%2,%3}, [%4];"
                 : "=f"(v.x), "=f"(v.y), "=f"(v.z), "=f"(v.w) : "l"(p));
    return v;
}
__device__ __forceinline__ float ldg_stream_f(const float* p) {
    float v;
    asm volatile("ld.global.cs.f32 %0, [%1];" : "=f"(v) : "l"(p));
    return v;
}
__device__ __forceinline__ int ldg_stream_i(const int* p) {
    int v;
    asm volatile("ld.global.cs.s32 %0, [%1];" : "=r"(v) : "l"(p));
    return v;
}
__device__ __forceinline__ void stg_last_u4(void* p, uint4 v, uint64_t pol) {
    asm volatile("st.global.L2::cache_hint.v4.b32 [%0], {%1,%2,%3,%4}, %5;"
                 :: "l"(p), "r"(v.x), "r"(v.y), "r"(v.z), "r"(v.w), "l"(pol));
}
__device__ __forceinline__ void stg_last_f4(float4* p, float4 v, uint64_t pol) {
    asm volatile("st.global.L2::cache_hint.v4.f32 [%0], {%1,%2,%3,%4}, %5;"
                 :: "l"(p), "f"(v.x), "f"(v.y), "f"(v.z), "f"(v.w), "l"(pol));
}
__device__ __forceinline__ void stg_stream_f4(float4* p, float4 v) {
    asm volatile("st.global.cs.v4.f32 [%0], {%1,%2,%3,%4};"
                 :: "l"(p), "f"(v.x), "f"(v.y), "f"(v.z), "f"(v.w));
}

// ---- k1: table prep: emb fp32->fp16, cp->float4; PDL trigger at end ----
__global__ void prep_kernel(const float* __restrict__ emb,
                            const float* __restrict__ cp,
                            int n8, int n_vox)
{
    int i = blockIdx.x * blockDim.x + threadIdx.x;
    uint64_t pol = make_evict_last_policy();
    if (i < n8) {
        const float4* src = reinterpret_cast<const float4*>(emb) + (size_t)i * 2;
        float4 a = ldg_stream_f4(&src[0]);
        float4 b = ldg_stream_f4(&src[1]);
        __half2 h0 = __floats2half2_rn(a.x, a.y);
        __half2 h1 = __floats2half2_rn(a.z, a.w);
        __half2 h2 = __floats2half2_rn(b.x, b.y);
        __half2 h3 = __floats2half2_rn(b.z, b.w);
        uint4 packed;
        packed.x = *reinterpret_cast<uint32_t*>(&h0);
        packed.y = *reinterpret_cast<uint32_t*>(&h1);
        packed.z = *reinterpret_cast<uint32_t*>(&h2);
        packed.w = *reinterpret_cast<uint32_t*>(&h3);
        stg_last_u4(reinterpret_cast<uint4*>(g_emb_h) + i, packed, pol);
    } else {
        int j = i - n8;
        if (j < n_vox) {
            float x = ldg_stream_f(&cp[3 * j + 0]);
            float y = ldg_stream_f(&cp[3 * j + 1]);
            float z = ldg_stream_f(&cp[3 * j + 2]);
            stg_last_f4(&g_cp4[j], make_float4(x, y, z, 0.0f), pol);
        }
    }
    // allow dependent (main) kernel blocks to launch
    asm volatile("griddepcontrol.launch_dependents;");
}

// ---- k2: main — exact R6 structure; PDL wait before table reads ----
__global__ void __launch_bounds__(256, 8) voxel_interp_kernel(
    const float*  __restrict__ pts,
    const int*    __restrict__ p2v_idx,
    const int*    __restrict__ center2corner,
    const float*  __restrict__ voxel_size,
    float*        __restrict__ out,
    int n_pts)
{
    int tid   = blockIdx.x * blockDim.x + threadIdx.x;
    int point = tid >> 2;
    int sub   = tid & 3;
    if (point >= n_pts) {
        asm volatile("griddepcontrol.wait;" ::: "memory");
        return;
    }

    uint64_t pol = make_evict_last_policy();

    // ---- prep-independent loads (overlap with prep tail) ----
    int v = ldg_stream_i(&p2v_idx[point]);
    float Px = ldg_stream_f(&pts[3 * (size_t)point + 0]);
    float Py = ldg_stream_f(&pts[3 * (size_t)point + 1]);
    float Pz = ldg_stream_f(&pts[3 * (size_t)point + 2]);
    float inv_vs = 1.0f / __ldg(&voxel_size[0]);
    int cidx[8];
    ldg_last_i8(center2corner + (size_t)v * 8, cidx);

    // ---- wait for prep's tables ----
    asm volatile("griddepcontrol.wait;" ::: "memory");

    float4 cp = ldg_last_f4(&g_cp4[v], pol);

    // batch all 8 embedding gathers before any FMA (MLP ~8)
    uint2 r[8];
    #pragma unroll
    for (int c = 0; c < 8; ++c) {
        const char* rowp = reinterpret_cast<const char*>(g_emb_h)
                         + (size_t)cidx[c] * 32 + sub * 8;
        r[c] = ldg_last_u2(rowp, pol);
    }

    float px = (Px - cp.x) * inv_vs + 0.5f;
    float py = (Py - cp.y) * inv_vs + 0.5f;
    float pz = (Pz - cp.z) * inv_vs + 0.5f;

    // corner c (meshgrid ij): bit2 -> x, bit1 -> y, bit0 -> z
    float wx[2] = {1.0f - px, px};
    float wy[2] = {1.0f - py, py};
    float wz[2] = {1.0f - pz, pz};

    float4 acc = make_float4(0.0f, 0.0f, 0.0f, 0.0f);
    #pragma unroll
    for (int c = 0; c < 8; ++c) {
        float w = wx[(c >> 2) & 1] * wy[(c >> 1) & 1] * wz[c & 1];
        float2 f01 = __half22float2(*reinterpret_cast<const __half2*>(&r[c].x));
        float2 f23 = __half22float2(*reinterpret_cast<const __half2*>(&r[c].y));
        acc.x = fmaf(w, f01.x, acc.x);
        acc.y = fmaf(w, f01.y, acc.y);
        acc.z = fmaf(w, f23.x, acc.z);
        acc.w = fmaf(w, f23.y, acc.w);
    }

    stg_stream_f4(reinterpret_cast<float4*>(out) + (size_t)point * 4 + sub, acc);
}

extern "C" void kernel_launch(void* const* d_in, const int* in_sizes, int n_in,
                              void* d_out, int out_size)
{
    const float* pts            = (const float*)d_in[0];
    const int*   p2v_idx        = (const int*)  d_in[1];
    const float* embeddings     = (const float*)d_in[2];
    const float* center_points  = (const float*)d_in[3];
    const int*   center2corner  = (const int*)  d_in[4];
    const float* voxel_size     = (const float*)d_in[5];
    float*       out            = (float*)d_out;

    int n8    = in_sizes[2] / 8;
    int n_vox = in_sizes[3] / 3;
    int n_pts = in_sizes[0] / 3;

    int prep_threads = n8 + n_vox;
    prep_kernel<<<(prep_threads + 255) / 256, 256>>>(
        embeddings, center_points, n8, n_vox);

    // main with Programmatic Dependent Launch (overlaps with prep tail)
    int total_threads = n_pts * 4;
    cudaLaunchConfig_t cfg = {};
    cfg.gridDim  = dim3((total_threads + 255) / 256);
    cfg.blockDim = dim3(256);
    cudaLaunchAttribute attrs[1];
    attrs[0].id = cudaLaunchAttributeProgrammaticStreamSerialization;
    attrs[0].val.programmaticStreamSerializationAllowed = 1;
    cfg.attrs = attrs;
    cfg.numAttrs = 1;
    cudaLaunchKernelEx(&cfg, voxel_interp_kernel,
                       pts, p2v_idx, center2corner, voxel_size, out, n_pts);
}